// round 1
// baseline (speedup 1.0000x reference)
#include <cuda_runtime.h>
#include <cstdint>

#define FULL_MASK 0xFFFFFFFFu

// Problem constants
#define NQ 8
#define DEPTH 3
#define FDIM 512
#define NCLS 10

// One warp simulates one batch element.
// Amplitude index = (lane << 3) | r  (qubits 0..2 in registers r-bits, 3..7 in lane bits)
__global__ void __launch_bounds__(256) qiskit_head_kernel(
    const float* __restrict__ x,       // (B, 512)
    const float* __restrict__ proj_w,  // (8, 512)
    const float* __restrict__ qnn_w,   // (72,)
    const float* __restrict__ out_w,   // (10, 8)
    const float* __restrict__ out_b,   // (10,)
    float* __restrict__ out,           // (B, 10)
    int B)
{
    __shared__ __align__(16) float s_pw[NQ * FDIM];   // 16 KB
    __shared__ float2 s_g[DEPTH * NQ][4];             // fused RX*RY*RX gates
    __shared__ float  s_ow[NCLS * NQ];
    __shared__ float  s_ob[NCLS];

    const int tid  = threadIdx.x;
    const int lane = tid & 31;
    const int warp = tid >> 5;

    // ---- block-shared setup ----
    #pragma unroll 4
    for (int i = tid; i < NQ * FDIM; i += 256) s_pw[i] = proj_w[i];
    if (tid < NCLS * NQ) s_ow[tid] = out_w[tid];
    if (tid < NCLS)      s_ob[tid] = out_b[tid];
    if (tid < DEPTH * NQ) {
        float w0 = qnn_w[tid * 3 + 0];
        float w1 = qnn_w[tid * 3 + 1];
        float w2 = qnn_w[tid * 3 + 2];
        float c0, s0, c1, s1, c2, s2;
        sincosf(0.5f * w0, &s0, &c0);
        sincosf(0.5f * w1, &s1, &c1);
        sincosf(0.5f * w2, &s2, &c2);
        // A = RY(w1) * RX(w0);  RX = [[c,-is],[-is,c]], RY = [[c,-s],[s,c]]
        float2 A00 = { c1 * c0,  s1 * s0};
        float2 A01 = {-s1 * c0, -c1 * s0};
        float2 A10 = { s1 * c0, -c1 * s0};
        float2 A11 = { c1 * c0, -s1 * s0};
        // M = RX(w2) * A ;  (-i s2)*(x+iy) = (s2*y, -s2*x)
        s_g[tid][0] = make_float2(c2 * A00.x + s2 * A10.y, c2 * A00.y - s2 * A10.x);
        s_g[tid][1] = make_float2(c2 * A01.x + s2 * A11.y, c2 * A01.y - s2 * A11.x);
        s_g[tid][2] = make_float2(c2 * A10.x + s2 * A00.y, c2 * A10.y - s2 * A00.x);
        s_g[tid][3] = make_float2(c2 * A11.x + s2 * A01.y, c2 * A11.y - s2 * A01.x);
    }
    __syncthreads();

    const int b = blockIdx.x * 8 + warp;
    if (b >= B) return;   // warp-uniform

    // ---- projection: angles[q] = tanh(x[b] . proj_w[q]) * pi/2 ----
    float acc[NQ];
    #pragma unroll
    for (int q = 0; q < NQ; q++) acc[q] = 0.f;

    const float4* xr = (const float4*)(x + (size_t)b * FDIM);
    #pragma unroll
    for (int ch = 0; ch < 4; ch++) {
        float4 xv = xr[ch * 32 + lane];
        #pragma unroll
        for (int q = 0; q < NQ; q++) {
            float4 wv = *(const float4*)&s_pw[q * FDIM + ch * 128 + lane * 4];
            acc[q] += xv.x * wv.x + xv.y * wv.y + xv.z * wv.z + xv.w * wv.w;
        }
    }
    #pragma unroll
    for (int off = 16; off > 0; off >>= 1) {
        #pragma unroll
        for (int q = 0; q < NQ; q++)
            acc[q] += __shfl_xor_sync(FULL_MASK, acc[q], off);
    }

    // half-angles: tanh(dot) * pi/4
    float cq[NQ], sq[NQ];
    #pragma unroll
    for (int q = 0; q < NQ; q++) {
        float h = tanhf(acc[q]) * 0.78539816339744830962f;
        sincosf(h, &sq[q], &cq[q]);
    }

    // ---- initial state: RY-encoded |0..0> is a product state ----
    float lp = 1.f;
    #pragma unroll
    for (int k = 0; k < 5; k++) lp *= ((lane >> k) & 1) ? sq[k + 3] : cq[k + 3];

    float ar[8], ai[8];
    #pragma unroll
    for (int r = 0; r < 8; r++) {
        float rp = ((r & 1) ? sq[0] : cq[0]) *
                   ((r & 2) ? sq[1] : cq[1]) *
                   ((r & 4) ? sq[2] : cq[2]);
        ar[r] = lp * rp;
        ai[r] = 0.f;
    }

    // ---- circuit layers ----
    #pragma unroll
    for (int l = 0; l < DEPTH; l++) {
        // fused 1q gates on register qubits 0..2
        #pragma unroll
        for (int q = 0; q < 3; q++) {
            const int g = l * NQ + q;
            float2 u00 = s_g[g][0], u01 = s_g[g][1], u10 = s_g[g][2], u11 = s_g[g][3];
            const int m = 1 << q;
            #pragma unroll
            for (int r = 0; r < 8; r++) {
                if (!(r & m)) {
                    int r1 = r | m;
                    float a0r = ar[r],  a0i = ai[r];
                    float a1r = ar[r1], a1i = ai[r1];
                    ar[r]  = u00.x * a0r - u00.y * a0i + u01.x * a1r - u01.y * a1i;
                    ai[r]  = u00.x * a0i + u00.y * a0r + u01.x * a1i + u01.y * a1r;
                    ar[r1] = u10.x * a0r - u10.y * a0i + u11.x * a1r - u11.y * a1i;
                    ai[r1] = u10.x * a0i + u10.y * a0r + u11.x * a1i + u11.y * a1r;
                }
            }
        }
        // fused 1q gates on lane qubits 3..7 (shfl_xor pairing)
        #pragma unroll
        for (int q = 3; q < 8; q++) {
            const int g = l * NQ + q;
            const int lm = 1 << (q - 3);
            const int bit = (lane >> (q - 3)) & 1;
            float2 e0 = bit ? s_g[g][3] : s_g[g][0];  // coeff for own amp
            float2 e1 = bit ? s_g[g][2] : s_g[g][1];  // coeff for partner amp
            #pragma unroll
            for (int r = 0; r < 8; r++) {
                float pr = __shfl_xor_sync(FULL_MASK, ar[r], lm);
                float pi = __shfl_xor_sync(FULL_MASK, ai[r], lm);
                float nr = e0.x * ar[r] - e0.y * ai[r] + e1.x * pr - e1.y * pi;
                float ni = e0.x * ai[r] + e0.y * ar[r] + e1.x * pi + e1.y * pr;
                ar[r] = nr; ai[r] = ni;
            }
        }
        // CNOT(0,1): bit0 controls, flip bit1 -> swap (1,3),(5,7)
        { float t;
          t=ar[1]; ar[1]=ar[3]; ar[3]=t;  t=ai[1]; ai[1]=ai[3]; ai[3]=t;
          t=ar[5]; ar[5]=ar[7]; ar[7]=t;  t=ai[5]; ai[5]=ai[7]; ai[7]=t; }
        // CNOT(1,2): bit1 controls, flip bit2 -> swap (2,6),(3,7)
        { float t;
          t=ar[2]; ar[2]=ar[6]; ar[6]=t;  t=ai[2]; ai[2]=ai[6]; ai[6]=t;
          t=ar[3]; ar[3]=ar[7]; ar[7]=t;  t=ai[3]; ai[3]=ai[7]; ai[7]=t; }
        // CNOT(2,3): reg bit2 controls, flip lane bit0 -> registers 4..7 exchange with lane^1
        #pragma unroll
        for (int r = 4; r < 8; r++) {
            ar[r] = __shfl_xor_sync(FULL_MASK, ar[r], 1);
            ai[r] = __shfl_xor_sync(FULL_MASK, ai[r], 1);
        }
        // CNOT(q,q+1) for q=3..6: lane-bit control, lane-bit target (index permutation)
        #pragma unroll
        for (int q = 3; q < 7; q++) {
            const int cb = q - 3, tb = q - 2;
            const int src = lane ^ (((lane >> cb) & 1) << tb);
            #pragma unroll
            for (int r = 0; r < 8; r++) {
                ar[r] = __shfl_sync(FULL_MASK, ar[r], src);
                ai[r] = __shfl_sync(FULL_MASK, ai[r], src);
            }
        }
        // CNOT(7,0): lane bit4 controls, flip reg bit0 -> conditional register swap
        if ((lane >> 4) & 1) {
            float t;
            t=ar[0]; ar[0]=ar[1]; ar[1]=t;  t=ai[0]; ai[0]=ai[1]; ai[1]=t;
            t=ar[2]; ar[2]=ar[3]; ar[3]=t;  t=ai[2]; ai[2]=ai[3]; ai[3]=t;
            t=ar[4]; ar[4]=ar[5]; ar[5]=t;  t=ai[4]; ai[4]=ai[5]; ai[5]=t;
            t=ar[6]; ar[6]=ar[7]; ar[7]=t;  t=ai[6]; ai[6]=ai[7]; ai[7]=t;
        }
    }

    // ---- PauliZ expectations ----
    float p[8];
    #pragma unroll
    for (int r = 0; r < 8; r++) p[r] = ar[r] * ar[r] + ai[r] * ai[r];

    float sum[NQ];
    float tot = 0.f;
    #pragma unroll
    for (int r = 0; r < 8; r++) tot += p[r];
    sum[0] = p[0] - p[1] + p[2] - p[3] + p[4] - p[5] + p[6] - p[7];
    sum[1] = p[0] + p[1] - p[2] - p[3] + p[4] + p[5] - p[6] - p[7];
    sum[2] = p[0] + p[1] + p[2] + p[3] - p[4] - p[5] - p[6] - p[7];
    #pragma unroll
    for (int q = 3; q < 8; q++)
        sum[q] = ((lane >> (q - 3)) & 1) ? -tot : tot;

    #pragma unroll
    for (int off = 16; off > 0; off >>= 1) {
        #pragma unroll
        for (int q = 0; q < NQ; q++)
            sum[q] += __shfl_xor_sync(FULL_MASK, sum[q], off);
    }

    // ---- output head: (B,8) @ (8,10)^T + b ----
    if (lane < NCLS) {
        float o = s_ob[lane];
        #pragma unroll
        for (int q = 0; q < NQ; q++) o += sum[q] * s_ow[lane * NQ + q];
        out[(size_t)b * NCLS + lane] = o;
    }
}

extern "C" void kernel_launch(void* const* d_in, const int* in_sizes, int n_in,
                              void* d_out, int out_size) {
    const float* x      = (const float*)d_in[0];
    const float* proj_w = (const float*)d_in[1];
    const float* qnn_w  = (const float*)d_in[2];
    const float* out_w  = (const float*)d_in[3];
    const float* out_b  = (const float*)d_in[4];
    float* out = (float*)d_out;

    int B = in_sizes[0] / FDIM;           // 8192
    int blocks = (B + 7) / 8;             // 8 warps (batch elems) per block
    qiskit_head_kernel<<<blocks, 256>>>(x, proj_w, qnn_w, out_w, out_b, out, B);
}